// round 14
// baseline (speedup 1.0000x reference)
#include <cuda_runtime.h>
#include <cstdint>
#include <cstddef>

#define N_NODES 50000
#define N_EDGES 800000
#define NB_SCAN 196          // ceil(50000/256)
#define PC_BLOCKS 782        // ceil(50000/64)   precompute role (quarter-split)
#define CNT_BLOCKS 1563      // ceil(800000/512) count role (2 edges/thread)
#define PREP_BLOCKS 64       // prep role

// Scratch (device globals; zero-initialized at module load).
// INVARIANT: g_cnt and g_agg are all-zero at every kernel_launch entry
// (established by load-time zero-init, re-established by nodeB's tail).
__device__ __align__(16) float g_xw1[N_NODES * 64];   // x@W1[:64]+b1
__device__ __align__(16) float g_agg[N_NODES * 64];   // per-node sum of relu(h)
__device__ __align__(16) float g_wc[64 * 64];         // W2 @ W3[64:128,:]
__device__ float g_bc[64];                            // b2 @ W3[64:128,:]
__device__ int g_cnt[N_NODES];
__device__ int g_base[N_NODES];
__device__ int g_cursor[N_NODES];
__device__ __align__(16) int4 g_slot[N_EDGES];        // {src, e, dst, pad}, dst-sorted
__device__ int g_bsum[NB_SCAN];

typedef unsigned long long u64;

__device__ __forceinline__ u64 pack2(float v) {
    u64 r; asm("mov.b64 %0, {%1, %1};" : "=l"(r) : "f"(v)); return r;
}
__device__ __forceinline__ u64 pack2f(float lo, float hi) {
    u64 r; asm("mov.b64 %0, {%1, %2};" : "=l"(r) : "f"(lo), "f"(hi)); return r;
}
__device__ __forceinline__ void unpack2(u64 v, float &lo, float &hi) {
    asm("mov.b64 {%0, %1}, %2;" : "=f"(lo), "=f"(hi) : "l"(v));
}
__device__ __forceinline__ void ffma2(u64 &d, u64 a, u64 b) {
    asm("fma.rn.f32x2 %0, %1, %2, %0;" : "+l"(d) : "l"(a), "l"(b));
}
__device__ __forceinline__ void red_add_v2(float* addr, float vx, float vy) {
    asm volatile("red.global.add.v2.f32 [%0], {%1, %2};"
                 :: "l"(addr), "f"(vx), "f"(vy) : "memory");
}

// ---------------------------------------------------------------------------
// K1 (fused): block-role kernel, 256 threads.
//   blocks [0, PC_BLOCKS):            precompute (quarter-split: 4 thr/node)
//   blocks [PC_BLOCKS, +CNT_BLOCKS):  count in-degrees (2 edges/thread)
//   blocks [.., +PREP_BLOCKS):        prep Wc = W2@W3bot, bc = b2@W3bot
// ---------------------------------------------------------------------------
__global__ void __launch_bounds__(256) fusedA_kernel(
        const float* __restrict__ x,
        const float* __restrict__ W1,
        const float* __restrict__ b1,
        const int*   __restrict__ ei,
        const float* __restrict__ W2,
        const float* __restrict__ W3,
        const float* __restrict__ b2) {
    __shared__ ulonglong2 sW[64 * 16];   // 16 KB (precompute role)
    __shared__ ulonglong2 sb[16];
    __shared__ float sw2[64];            // prep role
    int b = blockIdx.x;
    int tid = threadIdx.x;

    if (b < PC_BLOCKS) {
        // ---- precompute role: node = b*64 + (tid>>2), quarter q = tid&3 ----
        const ulonglong2* W1v = reinterpret_cast<const ulonglong2*>(W1);
        for (int idx = tid; idx < 64 * 16; idx += 256) sW[idx] = W1v[idx];
        if (tid < 16) sb[tid] = reinterpret_cast<const ulonglong2*>(b1)[tid];
        __syncthreads();

        int nl = tid >> 2, q = tid & 3;
        int n = b * 64 + nl;
        if (n >= N_NODES) return;

        u64 acc[8];
        #pragma unroll
        for (int jj = 0; jj < 4; jj++) {
            ulonglong2 v = sb[q * 4 + jj];
            acc[2*jj] = v.x; acc[2*jj+1] = v.y;
        }

        const float4* xr = reinterpret_cast<const float4*>(x + (size_t)n * 64);
        #pragma unroll 1
        for (int c = 0; c < 4; c++) {
            float v[16];
            #pragma unroll
            for (int j = 0; j < 4; j++) {
                float4 f = xr[c * 4 + j];
                v[4*j] = f.x; v[4*j+1] = f.y; v[4*j+2] = f.z; v[4*j+3] = f.w;
            }
            #pragma unroll
            for (int i = 0; i < 16; i++) {
                u64 a = pack2(v[i]);
                #pragma unroll
                for (int jj = 0; jj < 4; jj++) {
                    ulonglong2 w = sW[(c * 16 + i) * 16 + q * 4 + jj];
                    ffma2(acc[2*jj], a, w.x);
                    ffma2(acc[2*jj+1], a, w.y);
                }
            }
        }
        ulonglong2* o = reinterpret_cast<ulonglong2*>(g_xw1 + (size_t)n * 64 + q * 16);
        #pragma unroll
        for (int jj = 0; jj < 4; jj++) {
            ulonglong2 v; v.x = acc[2*jj]; v.y = acc[2*jj+1]; o[jj] = v;
        }
    } else if (b < PC_BLOCKS + CNT_BLOCKS) {
        // ---- count role (512 edges per block, 2 per thread) ----
        int e = (b - PC_BLOCKS) * 512 + tid;
        if (e < N_EDGES) atomicAdd(&g_cnt[ei[N_EDGES + e]], 1);
        e += 256;
        if (e < N_EDGES) atomicAdd(&g_cnt[ei[N_EDGES + e]], 1);
    } else {
        // ---- prep role ----
        int i = b - (PC_BLOCKS + CNT_BLOCKS);
        int j = tid;
        if (j < 64) sw2[j] = W2[i * 64 + j];
        __syncthreads();
        if (j < 64) {
            float acc = 0.0f;
            #pragma unroll 8
            for (int k = 0; k < 64; k++)
                acc = fmaf(sw2[k], W3[(64 + k) * 64 + j], acc);
            g_wc[i * 64 + j] = acc;
            if (i == 0) {
                float accb = 0.0f;
                for (int k = 0; k < 64; k++)
                    accb = fmaf(b2[k], W3[(64 + k) * 64 + j], accb);
                g_bc[j] = accb;
            }
        }
    }
}

// ---------------------------------------------------------------------------
// K2a: per-block sums of g_cnt -> g_bsum
// ---------------------------------------------------------------------------
__global__ void __launch_bounds__(256) scanA_kernel() {
    int b = blockIdx.x, tid = threadIdx.x;
    int idx = b * 256 + tid;
    int v = (idx < N_NODES) ? g_cnt[idx] : 0;
    __shared__ int ws[8];
    #pragma unroll
    for (int o = 16; o > 0; o >>= 1) v += __shfl_down_sync(0xffffffffu, v, o);
    if ((tid & 31) == 0) ws[tid >> 5] = v;
    __syncthreads();
    if (tid == 0) {
        int s = 0;
        #pragma unroll
        for (int k = 0; k < 8; k++) s += ws[k];
        g_bsum[b] = s;
    }
}

// ---------------------------------------------------------------------------
// K2b (fused scanB+scanC): block offset from g_bsum[0..b), then local scan.
// ---------------------------------------------------------------------------
__global__ void __launch_bounds__(256) scanC_kernel() {
    int b = blockIdx.x, tid = threadIdx.x, lane = tid & 31, w = tid >> 5;
    __shared__ int ws[8];
    __shared__ int s_off;

    int p = (tid < b) ? g_bsum[tid] : 0;
    int pr = p;
    #pragma unroll
    for (int o = 16; o > 0; o >>= 1) pr += __shfl_down_sync(0xffffffffu, pr, o);
    if (lane == 0) ws[w] = pr;
    __syncthreads();
    if (tid == 0) {
        int s = 0;
        #pragma unroll
        for (int k = 0; k < 8; k++) s += ws[k];
        s_off = s;
    }
    __syncthreads();

    int idx = b * 256 + tid;
    int c = (idx < N_NODES) ? g_cnt[idx] : 0;
    int inc = c;
    #pragma unroll
    for (int o = 1; o < 32; o <<= 1) {
        int t = __shfl_up_sync(0xffffffffu, inc, o);
        if (lane >= o) inc += t;
    }
    __syncthreads();
    if (lane == 31) ws[w] = inc;
    __syncthreads();
    int off = s_off;
    #pragma unroll
    for (int k = 0; k < 8; k++) off += (k < w) ? ws[k] : 0;
    int base = off + inc - c;
    if (idx < N_NODES) { g_base[idx] = base; g_cursor[idx] = base; }
}

// ---------------------------------------------------------------------------
// K3: place edges into dst-sorted buckets — one scattered STG.128 per edge
// ---------------------------------------------------------------------------
__global__ void __launch_bounds__(256) place_kernel(const int* __restrict__ ei) {
    int e = blockIdx.x * 256 + threadIdx.x;
    int s = ei[e];
    int d = ei[N_EDGES + e];
    int pos = atomicAdd(&g_cursor[d], 1);
    g_slot[pos] = make_int4(s, e, d, 0);
}

// ---------------------------------------------------------------------------
// K4: aggregate over sorted slots (round-12/13 winner, unchanged).
// ---------------------------------------------------------------------------
__global__ void __launch_bounds__(128) aggregate_kernel(
        const float* __restrict__ ef,
        const float* __restrict__ W1) {
    __shared__ ulonglong2 sW1e[16 * 16];          // 4 KB
    __shared__ float sm[128 * 66];                // 33 KB, stride 66

    int tid = threadIdx.x;
    int warp = tid >> 5, lane = tid & 31;
    sW1e[tid * 2]     = reinterpret_cast<const ulonglong2*>(W1)[1024 + tid * 2];
    sW1e[tid * 2 + 1] = reinterpret_cast<const ulonglong2*>(W1)[1024 + tid * 2 + 1];

    int slot = blockIdx.x * 128 + tid;            // N_EDGES % 128 == 0
    int4 sl = g_slot[slot];
    int src = sl.x;
    int e   = sl.y;
    int d   = sl.z;

    int s0 = warp * 32;

    // Phase a: cooperative ef staging (4 lanes per row, float4 each)
    #pragma unroll
    for (int it = 0; it < 4; it++) {
        int r = (lane >> 2) + 8 * it;
        int q = lane & 3;
        int eid = __shfl_sync(0xffffffffu, e, r);
        float4 f = *reinterpret_cast<const float4*>(ef + (size_t)eid * 16 + q * 4);
        float* dst = sm + (s0 + r) * 66 + q * 4;
        dst[0] = f.x; dst[1] = f.y; dst[2] = f.z; dst[3] = f.w;
    }
    __syncwarp();

    // Phase b: own ef row -> registers
    float efr[16];
    {
        const float2* mef = reinterpret_cast<const float2*>(sm + tid * 66);
        #pragma unroll
        for (int m = 0; m < 8; m++) {
            float2 v = mef[m];
            efr[2*m] = v.x; efr[2*m+1] = v.y;
        }
    }
    __syncwarp();

    // Phase c: cooperative xw1 staging (coalesced LDG.64)
    #pragma unroll 8
    for (int r = 0; r < 32; r++) {
        int sr = __shfl_sync(0xffffffffu, src, r);
        float2 v = reinterpret_cast<const float2*>(g_xw1 + (size_t)sr * 64)[lane];
        *reinterpret_cast<float2*>(sm + (s0 + r) * 66 + 2 * lane) = v;
    }
    __syncthreads();   // sW1e + staged rows ready

    // Phase d: own row -> acc, += ef @ W1e, relu, write message in place
    u64 acc[32];
    const float2* myrow = reinterpret_cast<const float2*>(sm + tid * 66);
    #pragma unroll
    for (int j = 0; j < 32; j++) {
        float2 v = myrow[j];
        acc[j] = pack2f(v.x, v.y);
    }
    #pragma unroll
    for (int i = 0; i < 16; i++) {
        u64 a = pack2(efr[i]);
        #pragma unroll
        for (int j = 0; j < 16; j++) {
            ulonglong2 w = sW1e[i * 16 + j];
            ffma2(acc[2*j], a, w.x);
            ffma2(acc[2*j+1], a, w.y);
        }
    }
    float2* myrow_w = reinterpret_cast<float2*>(sm + tid * 66);
    #pragma unroll
    for (int j = 0; j < 32; j++) {
        float lo, hi; unpack2(acc[j], lo, hi);
        myrow_w[j] = make_float2(fmaxf(lo, 0.f), fmaxf(hi, 0.f));
    }
    __syncwarp();

    // Phase e: warp-chunk reduce over slots [s0, s0+32); dst via shfl
    float sx = 0.0f, sy = 0.0f;
    int dprev = __shfl_sync(0xffffffffu, d, 0);
    #pragma unroll 4
    for (int t = 0; t < 32; t++) {
        int dcur = __shfl_sync(0xffffffffu, d, t);
        if (dcur != dprev) {
            red_add_v2(g_agg + (size_t)dprev * 64 + 2 * lane, sx, sy);
            sx = 0.0f; sy = 0.0f;
            dprev = dcur;
        }
        float2 v = *reinterpret_cast<const float2*>(sm + (s0 + t) * 66 + 2 * lane);
        sx += v.x; sy += v.y;
    }
    red_add_v2(g_agg + (size_t)dprev * 64 + 2 * lane, sx, sy);
}

// ---------------------------------------------------------------------------
// K5: fused update+LN, QUARTER-SPLIT: 4 threads per node, 16 outputs each.
//   acc = x@W3[0:64,cols] + (aggsum*inv)@Wc[:,cols] + b3 + bc*(cnt*inv)
//   y = relu(acc) + x ; LN partials reduced across q via shfl_xor(1,2).
// Tail: re-zero g_cnt / g_agg (re-establishes the entry invariant).
// ---------------------------------------------------------------------------
__global__ void __launch_bounds__(256) nodeB_kernel(
        const float* __restrict__ x,
        const float* __restrict__ W3,
        const float* __restrict__ b3,
        const float* __restrict__ gamma,
        const float* __restrict__ beta,
        float* __restrict__ out) {
    __shared__ ulonglong2 sW[128 * 16];  // 32 KB: rows 0..63 W3 top, 64..127 Wc
    __shared__ float sb3[64], sbc[64], sg[64], sbt[64];
    int tid = threadIdx.x;
    const ulonglong2* W3v = reinterpret_cast<const ulonglong2*>(W3);
    const ulonglong2* Wcv = reinterpret_cast<const ulonglong2*>(g_wc);
    for (int idx = tid; idx < 64 * 16; idx += 256) {
        sW[idx] = W3v[idx];
        sW[64 * 16 + idx] = Wcv[idx];
    }
    if (tid < 64) { sb3[tid] = b3[tid]; sbc[tid] = g_bc[tid]; sg[tid] = gamma[tid]; sbt[tid] = beta[tid]; }
    __syncthreads();

    int nl = tid >> 2, q = tid & 3;
    int n0 = blockIdx.x * 64 + nl;
    bool valid = (n0 < N_NODES);
    int n = valid ? n0 : (N_NODES - 1);   // clamp; no early return (shfl below)

    float cnt = (float)g_cnt[n];
    float inv = 1.0f / (cnt + 1e-8f);
    float bs  = cnt * inv;

    u64 acc[8];
    #pragma unroll
    for (int jj = 0; jj < 8; jj++) {
        int col = q * 16 + 2 * jj;
        acc[jj] = pack2f(fmaf(bs, sbc[col], sb3[col]), fmaf(bs, sbc[col+1], sb3[col+1]));
    }

    const float4* xr = reinterpret_cast<const float4*>(x + (size_t)n * 64);
    const float4* ar = reinterpret_cast<const float4*>(g_agg + (size_t)n * 64);

    #pragma unroll 1
    for (int c = 0; c < 8; c++) {
        bool isx = (c < 4);
        const float4* p = isx ? (xr + c * 4) : (ar + (c - 4) * 4);
        float v[16];
        #pragma unroll
        for (int j = 0; j < 4; j++) {
            float4 f = p[j];
            v[4*j] = f.x; v[4*j+1] = f.y; v[4*j+2] = f.z; v[4*j+3] = f.w;
        }
        if (!isx) {
            #pragma unroll
            for (int j = 0; j < 16; j++) v[j] *= inv;
        }
        #pragma unroll
        for (int i = 0; i < 16; i++) {
            u64 a = pack2(v[i]);
            #pragma unroll
            for (int jj = 0; jj < 4; jj++) {
                ulonglong2 w = sW[(c * 16 + i) * 16 + q * 4 + jj];
                ffma2(acc[2*jj], a, w.x);
                ffma2(acc[2*jj+1], a, w.y);
            }
        }
    }

    // relu + residual on this quarter's columns
    float u[16];
    const float4* xq = reinterpret_cast<const float4*>(x + (size_t)n * 64 + q * 16);
    #pragma unroll
    for (int jj = 0; jj < 4; jj++) {
        float4 f = xq[jj];
        float a0, a1, a2, a3;
        unpack2(acc[2*jj],   a0, a1);
        unpack2(acc[2*jj+1], a2, a3);
        u[4*jj]   = fmaxf(a0, 0.0f) + f.x;
        u[4*jj+1] = fmaxf(a1, 0.0f) + f.y;
        u[4*jj+2] = fmaxf(a2, 0.0f) + f.z;
        u[4*jj+3] = fmaxf(a3, 0.0f) + f.w;
    }

    // LN: quarter partials, reduce across the 4 q-mates (adjacent lanes)
    float s = 0.0f, ss = 0.0f;
    #pragma unroll
    for (int j = 0; j < 16; j++) { s += u[j]; ss = fmaf(u[j], u[j], ss); }
    s  += __shfl_xor_sync(0xffffffffu, s, 1);
    ss += __shfl_xor_sync(0xffffffffu, ss, 1);
    s  += __shfl_xor_sync(0xffffffffu, s, 2);
    ss += __shfl_xor_sync(0xffffffffu, ss, 2);

    float mu  = s * (1.0f / 64.0f);
    float var = ss * (1.0f / 64.0f) - mu * mu;
    float r   = rsqrtf(var + 1e-5f);

    if (valid) {
        float4* o  = reinterpret_cast<float4*>(out + (size_t)n * 64 + q * 16);
        float4* az = reinterpret_cast<float4*>(g_agg + (size_t)n * 64 + q * 16);
        float4 z = make_float4(0.f, 0.f, 0.f, 0.f);
        #pragma unroll
        for (int jj = 0; jj < 4; jj++) {
            int col = q * 16 + 4 * jj;
            float4 v;
            v.x = (u[4*jj]   - mu) * r * sg[col]   + sbt[col];
            v.y = (u[4*jj+1] - mu) * r * sg[col+1] + sbt[col+1];
            v.z = (u[4*jj+2] - mu) * r * sg[col+2] + sbt[col+2];
            v.w = (u[4*jj+3] - mu) * r * sg[col+3] + sbt[col+3];
            o[jj] = v;
            az[jj] = z;
        }
        if (q == 0) g_cnt[n] = 0;
    }
}

// ---------------------------------------------------------------------------
extern "C" void kernel_launch(void* const* d_in, const int* in_sizes, int n_in,
                              void* d_out, int out_size) {
    const float* x     = (const float*)d_in[0];
    const int*   ei    = (const int*)  d_in[1];
    const float* ef    = (const float*)d_in[2];
    const float* W1    = (const float*)d_in[3];
    const float* b1    = (const float*)d_in[4];
    const float* W2    = (const float*)d_in[5];
    const float* b2    = (const float*)d_in[6];
    const float* W3    = (const float*)d_in[7];
    const float* b3    = (const float*)d_in[8];
    const float* gamma = (const float*)d_in[9];
    const float* beta  = (const float*)d_in[10];
    float* out = (float*)d_out;

    (void)in_sizes; (void)n_in; (void)out_size;

    fusedA_kernel<<<PC_BLOCKS + CNT_BLOCKS + PREP_BLOCKS, 256>>>(
        x, W1, b1, ei, W2, W3, b2);
    scanA_kernel<<<NB_SCAN, 256>>>();
    scanC_kernel<<<NB_SCAN, 256>>>();
    place_kernel<<<N_EDGES / 256, 256>>>(ei);
    aggregate_kernel<<<N_EDGES / 128, 128>>>(ef, W1);
    nodeB_kernel<<<(N_NODES + 63) / 64, 256>>>(x, W3, b3, gamma, beta, out);
}

// round 15
// speedup vs baseline: 1.4390x; 1.4390x over previous
#include <cuda_runtime.h>
#include <cstdint>
#include <cstddef>

#define N_NODES 50000
#define N_EDGES 800000
#define NB_SCAN 196          // ceil(50000/256)
#define PC_BLOCKS 391        // ceil(50000/128)  precompute role
#define CNT_BLOCKS 3125      // 800000/256       count role
#define PREP_BLOCKS 64       // prep role

// Scratch (device globals; zero-initialized at module load).
// INVARIANT: g_cnt and g_agg are all-zero at every kernel_launch entry
// (established by load-time zero-init, re-established by nodeB's tail).
__device__ __align__(16) float g_xw1[N_NODES * 64];   // x@W1[:64]+b1
__device__ __align__(16) float g_agg[N_NODES * 64];   // per-node sum of relu(h)
__device__ __align__(16) float g_wc[64 * 64];         // W2 @ W3[64:128,:]
__device__ float g_bc[64];                            // b2 @ W3[64:128,:]
__device__ int g_cnt[N_NODES];
__device__ int g_base[N_NODES];
__device__ int g_cursor[N_NODES];
__device__ __align__(16) int4 g_slot[N_EDGES];        // {src, e, dst, pad}, dst-sorted
__device__ int g_bsum[NB_SCAN];

typedef unsigned long long u64;

__device__ __forceinline__ u64 pack2(float v) {
    u64 r; asm("mov.b64 %0, {%1, %1};" : "=l"(r) : "f"(v)); return r;
}
__device__ __forceinline__ u64 pack2f(float lo, float hi) {
    u64 r; asm("mov.b64 %0, {%1, %2};" : "=l"(r) : "f"(lo), "f"(hi)); return r;
}
__device__ __forceinline__ void unpack2(u64 v, float &lo, float &hi) {
    asm("mov.b64 {%0, %1}, %2;" : "=f"(lo), "=f"(hi) : "l"(v));
}
__device__ __forceinline__ void ffma2(u64 &d, u64 a, u64 b) {
    asm("fma.rn.f32x2 %0, %1, %2, %0;" : "+l"(d) : "l"(a), "l"(b));
}
__device__ __forceinline__ void red_add_v2(float* addr, float vx, float vy) {
    asm volatile("red.global.add.v2.f32 [%0], {%1, %2};"
                 :: "l"(addr), "f"(vx), "f"(vy) : "memory");
}

// ---------------------------------------------------------------------------
// K1 (fused): block-role kernel.
//   blocks [0, PC_BLOCKS):              precompute  g_xw1 = x@W1[:64]+b1
//   blocks [PC_BLOCKS, +CNT_BLOCKS):    count in-degrees (g_cnt zero at entry)
//   blocks [.., +PREP_BLOCKS):          prep Wc = W2@W3bot, bc = b2@W3bot
// ---------------------------------------------------------------------------
__global__ void __launch_bounds__(128) fusedA_kernel(
        const float* __restrict__ x,
        const float* __restrict__ W1,
        const float* __restrict__ b1,
        const int*   __restrict__ ei,
        const float* __restrict__ W2,
        const float* __restrict__ W3,
        const float* __restrict__ b2) {
    __shared__ ulonglong2 sW[64 * 16];   // 16 KB (precompute role)
    __shared__ ulonglong2 sb[16];
    __shared__ float sw2[64];            // prep role
    int b = blockIdx.x;
    int tid = threadIdx.x;

    if (b < PC_BLOCKS) {
        // ---- precompute role ----
        const ulonglong2* W1v = reinterpret_cast<const ulonglong2*>(W1);
        for (int idx = tid; idx < 64 * 16; idx += 128) sW[idx] = W1v[idx];
        if (tid < 16) sb[tid] = reinterpret_cast<const ulonglong2*>(b1)[tid];
        __syncthreads();

        int n = b * 128 + tid;
        if (n >= N_NODES) return;

        u64 acc[32];
        #pragma unroll
        for (int j = 0; j < 16; j++) { ulonglong2 v = sb[j]; acc[2*j] = v.x; acc[2*j+1] = v.y; }

        const float4* xr = reinterpret_cast<const float4*>(x + (size_t)n * 64);
        #pragma unroll 1
        for (int c = 0; c < 2; c++) {
            float v[32];
            #pragma unroll
            for (int j = 0; j < 8; j++) {
                float4 f = xr[c * 8 + j];
                v[4*j] = f.x; v[4*j+1] = f.y; v[4*j+2] = f.z; v[4*j+3] = f.w;
            }
            #pragma unroll
            for (int i = 0; i < 32; i++) {
                u64 a = pack2(v[i]);
                #pragma unroll
                for (int j = 0; j < 16; j++) {
                    ulonglong2 w = sW[(c * 32 + i) * 16 + j];
                    ffma2(acc[2*j], a, w.x);
                    ffma2(acc[2*j+1], a, w.y);
                }
            }
        }
        ulonglong2* o = reinterpret_cast<ulonglong2*>(g_xw1 + (size_t)n * 64);
        #pragma unroll
        for (int j = 0; j < 16; j++) {
            ulonglong2 v; v.x = acc[2*j]; v.y = acc[2*j+1]; o[j] = v;
        }
    } else if (b < PC_BLOCKS + CNT_BLOCKS) {
        // ---- count role (256 edges per block) ----
        int e = (b - PC_BLOCKS) * 256 + tid;
        atomicAdd(&g_cnt[ei[N_EDGES + e]], 1);
        atomicAdd(&g_cnt[ei[N_EDGES + e + 128]], 1);
    } else {
        // ---- prep role ----
        int i = b - (PC_BLOCKS + CNT_BLOCKS);
        int j = tid;
        if (j < 64) sw2[j] = W2[i * 64 + j];
        __syncthreads();
        if (j < 64) {
            float acc = 0.0f;
            #pragma unroll 8
            for (int k = 0; k < 64; k++)
                acc = fmaf(sw2[k], W3[(64 + k) * 64 + j], acc);
            g_wc[i * 64 + j] = acc;
            if (i == 0) {
                float accb = 0.0f;
                for (int k = 0; k < 64; k++)
                    accb = fmaf(b2[k], W3[(64 + k) * 64 + j], accb);
                g_bc[j] = accb;
            }
        }
    }
}

// ---------------------------------------------------------------------------
// K2a: per-block sums of g_cnt -> g_bsum
// ---------------------------------------------------------------------------
__global__ void __launch_bounds__(256) scanA_kernel() {
    int b = blockIdx.x, tid = threadIdx.x;
    int idx = b * 256 + tid;
    int v = (idx < N_NODES) ? g_cnt[idx] : 0;
    __shared__ int ws[8];
    #pragma unroll
    for (int o = 16; o > 0; o >>= 1) v += __shfl_down_sync(0xffffffffu, v, o);
    if ((tid & 31) == 0) ws[tid >> 5] = v;
    __syncthreads();
    if (tid == 0) {
        int s = 0;
        #pragma unroll
        for (int k = 0; k < 8; k++) s += ws[k];
        g_bsum[b] = s;
    }
}

// ---------------------------------------------------------------------------
// K2b (fused scanB+scanC): block offset from g_bsum[0..b), then local scan.
// ---------------------------------------------------------------------------
__global__ void __launch_bounds__(256) scanC_kernel() {
    int b = blockIdx.x, tid = threadIdx.x, lane = tid & 31, w = tid >> 5;
    __shared__ int ws[8];
    __shared__ int s_off;

    int p = (tid < b) ? g_bsum[tid] : 0;
    int pr = p;
    #pragma unroll
    for (int o = 16; o > 0; o >>= 1) pr += __shfl_down_sync(0xffffffffu, pr, o);
    if (lane == 0) ws[w] = pr;
    __syncthreads();
    if (tid == 0) {
        int s = 0;
        #pragma unroll
        for (int k = 0; k < 8; k++) s += ws[k];
        s_off = s;
    }
    __syncthreads();

    int idx = b * 256 + tid;
    int c = (idx < N_NODES) ? g_cnt[idx] : 0;
    int inc = c;
    #pragma unroll
    for (int o = 1; o < 32; o <<= 1) {
        int t = __shfl_up_sync(0xffffffffu, inc, o);
        if (lane >= o) inc += t;
    }
    __syncthreads();
    if (lane == 31) ws[w] = inc;
    __syncthreads();
    int off = s_off;
    #pragma unroll
    for (int k = 0; k < 8; k++) off += (k < w) ? ws[k] : 0;
    int base = off + inc - c;
    if (idx < N_NODES) { g_base[idx] = base; g_cursor[idx] = base; }
}

// ---------------------------------------------------------------------------
// K3: place — 4 edges per thread so 4 ATOMG are in flight (MLP 4).
// ---------------------------------------------------------------------------
__global__ void __launch_bounds__(256) place_kernel(const int* __restrict__ ei) {
    int e0 = blockIdx.x * 1024 + threadIdx.x;

    int s[4], d[4], pos[4];
    bool v[4];
    #pragma unroll
    for (int k = 0; k < 4; k++) {
        int e = e0 + k * 256;
        v[k] = (e < N_EDGES);
        int ec = v[k] ? e : 0;
        s[k] = ei[ec];
        d[k] = ei[N_EDGES + ec];
    }
    #pragma unroll
    for (int k = 0; k < 4; k++)
        if (v[k]) pos[k] = atomicAdd(&g_cursor[d[k]], 1);
    #pragma unroll
    for (int k = 0; k < 4; k++)
        if (v[k]) g_slot[pos[k]] = make_int4(s[k], e0 + k * 256, d[k], 0);
}

// ---------------------------------------------------------------------------
// K4: aggregate over sorted slots. Block = 128 slots.
// Phase a: cooperative ef staging; b: ef->regs; c: cooperative xw1 staging;
// d: message compute in place; e: warp-chunk reduce (dst via shfl).
// ---------------------------------------------------------------------------
__global__ void __launch_bounds__(128) aggregate_kernel(
        const float* __restrict__ ef,
        const float* __restrict__ W1) {
    __shared__ ulonglong2 sW1e[16 * 16];          // 4 KB
    __shared__ float sm[128 * 66];                // 33 KB, stride 66

    int tid = threadIdx.x;
    int warp = tid >> 5, lane = tid & 31;
    sW1e[tid * 2]     = reinterpret_cast<const ulonglong2*>(W1)[1024 + tid * 2];
    sW1e[tid * 2 + 1] = reinterpret_cast<const ulonglong2*>(W1)[1024 + tid * 2 + 1];

    int slot = blockIdx.x * 128 + tid;            // N_EDGES % 128 == 0
    int4 sl = g_slot[slot];                       // {src, e, dst, pad} coalesced
    int src = sl.x;
    int e   = sl.y;
    int d   = sl.z;

    int s0 = warp * 32;

    // Phase a: cooperative ef staging (4 lanes per row, float4 each)
    #pragma unroll
    for (int it = 0; it < 4; it++) {
        int r = (lane >> 2) + 8 * it;
        int q = lane & 3;
        int eid = __shfl_sync(0xffffffffu, e, r);
        float4 f = *reinterpret_cast<const float4*>(ef + (size_t)eid * 16 + q * 4);
        float* dst = sm + (s0 + r) * 66 + q * 4;
        dst[0] = f.x; dst[1] = f.y; dst[2] = f.z; dst[3] = f.w;
    }
    __syncwarp();

    // Phase b: own ef row -> registers
    float efr[16];
    {
        const float2* mef = reinterpret_cast<const float2*>(sm + tid * 66);
        #pragma unroll
        for (int m = 0; m < 8; m++) {
            float2 v = mef[m];
            efr[2*m] = v.x; efr[2*m+1] = v.y;
        }
    }
    __syncwarp();

    // Phase c: cooperative xw1 staging (coalesced LDG.64)
    #pragma unroll 8
    for (int r = 0; r < 32; r++) {
        int sr = __shfl_sync(0xffffffffu, src, r);
        float2 v = reinterpret_cast<const float2*>(g_xw1 + (size_t)sr * 64)[lane];
        *reinterpret_cast<float2*>(sm + (s0 + r) * 66 + 2 * lane) = v;
    }
    __syncthreads();   // sW1e + staged rows ready

    // Phase d: own row -> acc, += ef @ W1e, relu, write message in place
    u64 acc[32];
    const float2* myrow = reinterpret_cast<const float2*>(sm + tid * 66);
    #pragma unroll
    for (int j = 0; j < 32; j++) {
        float2 v = myrow[j];
        acc[j] = pack2f(v.x, v.y);
    }
    #pragma unroll
    for (int i = 0; i < 16; i++) {
        u64 a = pack2(efr[i]);
        #pragma unroll
        for (int j = 0; j < 16; j++) {
            ulonglong2 w = sW1e[i * 16 + j];
            ffma2(acc[2*j], a, w.x);
            ffma2(acc[2*j+1], a, w.y);
        }
    }
    float2* myrow_w = reinterpret_cast<float2*>(sm + tid * 66);
    #pragma unroll
    for (int j = 0; j < 32; j++) {
        float lo, hi; unpack2(acc[j], lo, hi);
        myrow_w[j] = make_float2(fmaxf(lo, 0.f), fmaxf(hi, 0.f));
    }
    __syncwarp();      // warp-local messages visible

    // Phase e: warp-chunk reduce over slots [s0, s0+32); dst via shfl
    float sx = 0.0f, sy = 0.0f;
    int dprev = __shfl_sync(0xffffffffu, d, 0);
    #pragma unroll 4
    for (int t = 0; t < 32; t++) {
        int dcur = __shfl_sync(0xffffffffu, d, t);   // warp-uniform
        if (dcur != dprev) {                         // warp-uniform branch
            red_add_v2(g_agg + (size_t)dprev * 64 + 2 * lane, sx, sy);
            sx = 0.0f; sy = 0.0f;
            dprev = dcur;
        }
        float2 v = *reinterpret_cast<const float2*>(sm + (s0 + t) * 66 + 2 * lane);
        sx += v.x; sy += v.y;
    }
    red_add_v2(g_agg + (size_t)dprev * 64 + 2 * lane, sx, sy);
}

// ---------------------------------------------------------------------------
// K5: fused update+LN (nodeA folded via Wc/bc), M=2 node blocking.
// Tail: re-zero g_cnt / g_agg rows (re-establishes the entry invariant).
// ---------------------------------------------------------------------------
__global__ void __launch_bounds__(128) nodeB_kernel(
        const float* __restrict__ x,
        const float* __restrict__ W3,
        const float* __restrict__ b3,
        const float* __restrict__ gamma,
        const float* __restrict__ beta,
        float* __restrict__ out) {
    __shared__ ulonglong2 sW[128 * 16];  // 32 KB: rows 0..63 W3 top, 64..127 Wc
    __shared__ float sb3[64], sbc[64], sg[64], sbt[64];
    int tid = threadIdx.x;
    const ulonglong2* W3v = reinterpret_cast<const ulonglong2*>(W3);
    const ulonglong2* Wcv = reinterpret_cast<const ulonglong2*>(g_wc);
    for (int idx = tid; idx < 64 * 16; idx += 128) {
        sW[idx] = W3v[idx];
        sW[64 * 16 + idx] = Wcv[idx];
    }
    if (tid < 64) { sb3[tid] = b3[tid]; sbc[tid] = g_bc[tid]; sg[tid] = gamma[tid]; sbt[tid] = beta[tid]; }
    __syncthreads();

    int n0 = blockIdx.x * 256 + tid;
    int n1 = n0 + 128;
    bool vA = (n0 < N_NODES), vB = (n1 < N_NODES);
    int nA = vA ? n0 : 0, nB = vB ? n1 : 0;

    float cntA = (float)g_cnt[nA];
    float cntB = (float)g_cnt[nB];
    float invA = 1.0f / (cntA + 1e-8f), invB = 1.0f / (cntB + 1e-8f);
    float bsA = cntA * invA, bsB = cntB * invB;

    u64 accA[32], accB[32];
    #pragma unroll
    for (int j = 0; j < 32; j++) {
        accA[j] = pack2f(fmaf(bsA, sbc[2*j], sb3[2*j]), fmaf(bsA, sbc[2*j+1], sb3[2*j+1]));
        accB[j] = pack2f(fmaf(bsB, sbc[2*j], sb3[2*j]), fmaf(bsB, sbc[2*j+1], sb3[2*j+1]));
    }

    const float4* xA = reinterpret_cast<const float4*>(x + (size_t)nA * 64);
    const float4* xB = reinterpret_cast<const float4*>(x + (size_t)nB * 64);
    const float4* aA = reinterpret_cast<const float4*>(g_agg + (size_t)nA * 64);
    const float4* aB = reinterpret_cast<const float4*>(g_agg + (size_t)nB * 64);

    #pragma unroll 1
    for (int c = 0; c < 8; c++) {
        bool isx = (c < 4);
        const float4* pA = isx ? (xA + c * 4) : (aA + (c - 4) * 4);
        const float4* pB = isx ? (xB + c * 4) : (aB + (c - 4) * 4);
        float va[16], vb[16];
        #pragma unroll
        for (int j = 0; j < 4; j++) {
            float4 fa = pA[j];
            float4 fb = pB[j];
            va[4*j] = fa.x; va[4*j+1] = fa.y; va[4*j+2] = fa.z; va[4*j+3] = fa.w;
            vb[4*j] = fb.x; vb[4*j+1] = fb.y; vb[4*j+2] = fb.z; vb[4*j+3] = fb.w;
        }
        if (!isx) {
            #pragma unroll
            for (int j = 0; j < 16; j++) { va[j] *= invA; vb[j] *= invB; }
        }
        #pragma unroll
        for (int i = 0; i < 16; i++) {
            u64 a0 = pack2(va[i]);
            u64 a1 = pack2(vb[i]);
            #pragma unroll
            for (int j = 0; j < 16; j++) {
                ulonglong2 w = sW[(c * 16 + i) * 16 + j];
                ffma2(accA[2*j], a0, w.x); ffma2(accA[2*j+1], a0, w.y);
                ffma2(accB[2*j], a1, w.x); ffma2(accB[2*j+1], a1, w.y);
            }
        }
    }

    // finalize node A then node B (reuse registers); re-zero scratch
    float4 z = make_float4(0.f, 0.f, 0.f, 0.f);
    #pragma unroll 1
    for (int m = 0; m < 2; m++) {
        bool valid = m ? vB : vA;
        if (!valid) continue;
        int n = m ? n1 : n0;
        u64* acc = m ? accB : accA;
        const float4* xr = reinterpret_cast<const float4*>(x + (size_t)n * 64);

        float u[64];
        #pragma unroll
        for (int j = 0; j < 16; j++) {
            float4 f = xr[j];
            float a0, a1, a2, a3;
            unpack2(acc[2*j],   a0, a1);
            unpack2(acc[2*j+1], a2, a3);
            u[4*j]   = fmaxf(a0, 0.0f) + f.x;
            u[4*j+1] = fmaxf(a1, 0.0f) + f.y;
            u[4*j+2] = fmaxf(a2, 0.0f) + f.z;
            u[4*j+3] = fmaxf(a3, 0.0f) + f.w;
        }
        float s = 0.0f, ss = 0.0f;
        #pragma unroll
        for (int j = 0; j < 64; j++) { s += u[j]; ss = fmaf(u[j], u[j], ss); }
        float mu  = s * (1.0f / 64.0f);
        float var = ss * (1.0f / 64.0f) - mu * mu;
        float r   = rsqrtf(var + 1e-5f);

        float4* o = reinterpret_cast<float4*>(out + (size_t)n * 64);
        float4* az = reinterpret_cast<float4*>(g_agg + (size_t)n * 64);
        #pragma unroll
        for (int j = 0; j < 16; j++) {
            float4 v;
            v.x = (u[4*j]   - mu) * r * sg[4*j]   + sbt[4*j];
            v.y = (u[4*j+1] - mu) * r * sg[4*j+1] + sbt[4*j+1];
            v.z = (u[4*j+2] - mu) * r * sg[4*j+2] + sbt[4*j+2];
            v.w = (u[4*j+3] - mu) * r * sg[4*j+3] + sbt[4*j+3];
            o[j] = v;
            az[j] = z;
        }
        g_cnt[n] = 0;
    }
}

// ---------------------------------------------------------------------------
extern "C" void kernel_launch(void* const* d_in, const int* in_sizes, int n_in,
                              void* d_out, int out_size) {
    const float* x     = (const float*)d_in[0];
    const int*   ei    = (const int*)  d_in[1];
    const float* ef    = (const float*)d_in[2];
    const float* W1    = (const float*)d_in[3];
    const float* b1    = (const float*)d_in[4];
    const float* W2    = (const float*)d_in[5];
    const float* b2    = (const float*)d_in[6];
    const float* W3    = (const float*)d_in[7];
    const float* b3    = (const float*)d_in[8];
    const float* gamma = (const float*)d_in[9];
    const float* beta  = (const float*)d_in[10];
    float* out = (float*)d_out;

    (void)in_sizes; (void)n_in; (void)out_size;

    const int nb256 = (N_NODES + 255) / 256;

    fusedA_kernel<<<PC_BLOCKS + CNT_BLOCKS + PREP_BLOCKS, 128>>>(
        x, W1, b1, ei, W2, W3, b2);
    scanA_kernel<<<NB_SCAN, 256>>>();
    scanC_kernel<<<NB_SCAN, 256>>>();
    place_kernel<<<(N_EDGES + 1023) / 1024, 256>>>(ei);
    aggregate_kernel<<<N_EDGES / 128, 128>>>(ef, W1);
    nodeB_kernel<<<nb256, 128>>>(x, W3, b3, gamma, beta, out);
}

// round 16
// speedup vs baseline: 1.4851x; 1.0320x over previous
#include <cuda_runtime.h>
#include <cstdint>
#include <cstddef>

#define N_NODES 50000
#define N_EDGES 800000
#define NB_SCAN 196          // ceil(50000/256)
#define PC_BLOCKS 391        // ceil(50000/128)  precompute role
#define CNT_BLOCKS 3125      // 800000/256       count role
#define PREP_BLOCKS 64       // prep role

// Scratch (device globals; zero-initialized at module load).
// INVARIANT: g_cnt and g_agg are all-zero at every kernel_launch entry
// (established by load-time zero-init, re-established by nodeB's tail).
__device__ __align__(16) float g_xw1[N_NODES * 64];   // x@W1[:64]+b1
__device__ __align__(16) float g_agg[N_NODES * 64];   // per-node sum of relu(h)
__device__ __align__(16) float g_wc[64 * 64];         // W2 @ W3[64:128,:]
__device__ float g_bc[64];                            // b2 @ W3[64:128,:]
__device__ int g_cnt[N_NODES];
__device__ int g_base[N_NODES];
__device__ int g_rank[N_EDGES];                       // rank of edge within its dst bucket
__device__ __align__(16) int4 g_slot[N_EDGES];        // {src, e, dst, pad}, dst-sorted
__device__ int g_bsum[NB_SCAN];

typedef unsigned long long u64;

__device__ __forceinline__ u64 pack2(float v) {
    u64 r; asm("mov.b64 %0, {%1, %1};" : "=l"(r) : "f"(v)); return r;
}
__device__ __forceinline__ u64 pack2f(float lo, float hi) {
    u64 r; asm("mov.b64 %0, {%1, %2};" : "=l"(r) : "f"(lo), "f"(hi)); return r;
}
__device__ __forceinline__ void unpack2(u64 v, float &lo, float &hi) {
    asm("mov.b64 {%0, %1}, %2;" : "=f"(lo), "=f"(hi) : "l"(v));
}
__device__ __forceinline__ void ffma2(u64 &d, u64 a, u64 b) {
    asm("fma.rn.f32x2 %0, %1, %2, %0;" : "+l"(d) : "l"(a), "l"(b));
}
__device__ __forceinline__ void red_add_v2(float* addr, float vx, float vy) {
    asm volatile("red.global.add.v2.f32 [%0], {%1, %2};"
                 :: "l"(addr), "f"(vx), "f"(vy) : "memory");
}

// ---------------------------------------------------------------------------
// K1 (fused): block-role kernel.
//   blocks [0, PC_BLOCKS):              precompute  g_xw1 = x@W1[:64]+b1
//   blocks [PC_BLOCKS, +CNT_BLOCKS):    count in-degrees AND capture ranks
//   blocks [.., +PREP_BLOCKS):          prep Wc = W2@W3bot, bc = b2@W3bot
// ---------------------------------------------------------------------------
__global__ void __launch_bounds__(128) fusedA_kernel(
        const float* __restrict__ x,
        const float* __restrict__ W1,
        const float* __restrict__ b1,
        const int*   __restrict__ ei,
        const float* __restrict__ W2,
        const float* __restrict__ W3,
        const float* __restrict__ b2) {
    __shared__ ulonglong2 sW[64 * 16];   // 16 KB (precompute role)
    __shared__ ulonglong2 sb[16];
    __shared__ float sw2[64];            // prep role
    int b = blockIdx.x;
    int tid = threadIdx.x;

    if (b < PC_BLOCKS) {
        // ---- precompute role ----
        const ulonglong2* W1v = reinterpret_cast<const ulonglong2*>(W1);
        for (int idx = tid; idx < 64 * 16; idx += 128) sW[idx] = W1v[idx];
        if (tid < 16) sb[tid] = reinterpret_cast<const ulonglong2*>(b1)[tid];
        __syncthreads();

        int n = b * 128 + tid;
        if (n >= N_NODES) return;

        u64 acc[32];
        #pragma unroll
        for (int j = 0; j < 16; j++) { ulonglong2 v = sb[j]; acc[2*j] = v.x; acc[2*j+1] = v.y; }

        const float4* xr = reinterpret_cast<const float4*>(x + (size_t)n * 64);
        #pragma unroll 1
        for (int c = 0; c < 2; c++) {
            float v[32];
            #pragma unroll
            for (int j = 0; j < 8; j++) {
                float4 f = xr[c * 8 + j];
                v[4*j] = f.x; v[4*j+1] = f.y; v[4*j+2] = f.z; v[4*j+3] = f.w;
            }
            #pragma unroll
            for (int i = 0; i < 32; i++) {
                u64 a = pack2(v[i]);
                #pragma unroll
                for (int j = 0; j < 16; j++) {
                    ulonglong2 w = sW[(c * 32 + i) * 16 + j];
                    ffma2(acc[2*j], a, w.x);
                    ffma2(acc[2*j+1], a, w.y);
                }
            }
        }
        ulonglong2* o = reinterpret_cast<ulonglong2*>(g_xw1 + (size_t)n * 64);
        #pragma unroll
        for (int j = 0; j < 16; j++) {
            ulonglong2 v; v.x = acc[2*j]; v.y = acc[2*j+1]; o[j] = v;
        }
    } else if (b < PC_BLOCKS + CNT_BLOCKS) {
        // ---- count role (256 edges per block): rank = old count value ----
        int e0 = (b - PC_BLOCKS) * 256 + tid;
        int e1 = e0 + 128;
        int d0 = ei[N_EDGES + e0];
        int d1 = ei[N_EDGES + e1];
        g_rank[e0] = atomicAdd(&g_cnt[d0], 1);
        g_rank[e1] = atomicAdd(&g_cnt[d1], 1);
    } else {
        // ---- prep role ----
        int i = b - (PC_BLOCKS + CNT_BLOCKS);
        int j = tid;
        if (j < 64) sw2[j] = W2[i * 64 + j];
        __syncthreads();
        if (j < 64) {
            float acc = 0.0f;
            #pragma unroll 8
            for (int k = 0; k < 64; k++)
                acc = fmaf(sw2[k], W3[(64 + k) * 64 + j], acc);
            g_wc[i * 64 + j] = acc;
            if (i == 0) {
                float accb = 0.0f;
                for (int k = 0; k < 64; k++)
                    accb = fmaf(b2[k], W3[(64 + k) * 64 + j], accb);
                g_bc[j] = accb;
            }
        }
    }
}

// ---------------------------------------------------------------------------
// K2a: per-block sums of g_cnt -> g_bsum
// ---------------------------------------------------------------------------
__global__ void __launch_bounds__(256) scanA_kernel() {
    int b = blockIdx.x, tid = threadIdx.x;
    int idx = b * 256 + tid;
    int v = (idx < N_NODES) ? g_cnt[idx] : 0;
    __shared__ int ws[8];
    #pragma unroll
    for (int o = 16; o > 0; o >>= 1) v += __shfl_down_sync(0xffffffffu, v, o);
    if ((tid & 31) == 0) ws[tid >> 5] = v;
    __syncthreads();
    if (tid == 0) {
        int s = 0;
        #pragma unroll
        for (int k = 0; k < 8; k++) s += ws[k];
        g_bsum[b] = s;
    }
}

// ---------------------------------------------------------------------------
// K2b (fused scanB+scanC): block offset from g_bsum[0..b), then local scan.
// ---------------------------------------------------------------------------
__global__ void __launch_bounds__(256) scanC_kernel() {
    int b = blockIdx.x, tid = threadIdx.x, lane = tid & 31, w = tid >> 5;
    __shared__ int ws[8];
    __shared__ int s_off;

    int p = (tid < b) ? g_bsum[tid] : 0;
    int pr = p;
    #pragma unroll
    for (int o = 16; o > 0; o >>= 1) pr += __shfl_down_sync(0xffffffffu, pr, o);
    if (lane == 0) ws[w] = pr;
    __syncthreads();
    if (tid == 0) {
        int s = 0;
        #pragma unroll
        for (int k = 0; k < 8; k++) s += ws[k];
        s_off = s;
    }
    __syncthreads();

    int idx = b * 256 + tid;
    int c = (idx < N_NODES) ? g_cnt[idx] : 0;
    int inc = c;
    #pragma unroll
    for (int o = 1; o < 32; o <<= 1) {
        int t = __shfl_up_sync(0xffffffffu, inc, o);
        if (lane >= o) inc += t;
    }
    __syncthreads();
    if (lane == 31) ws[w] = inc;
    __syncthreads();
    int off = s_off;
    #pragma unroll
    for (int k = 0; k < 8; k++) off += (k < w) ? ws[k] : 0;
    int base = off + inc - c;
    if (idx < N_NODES) g_base[idx] = base;
}

// ---------------------------------------------------------------------------
// K3: place — ATOMIC-FREE: slot = g_base[dst] + g_rank[e]; one STG.128.
// ---------------------------------------------------------------------------
__global__ void __launch_bounds__(256) place_kernel(const int* __restrict__ ei) {
    int e = blockIdx.x * 256 + threadIdx.x;
    int s = ei[e];
    int d = ei[N_EDGES + e];
    int r = g_rank[e];
    int pos = g_base[d] + r;
    g_slot[pos] = make_int4(s, e, d, 0);
}

// ---------------------------------------------------------------------------
// K4: aggregate over sorted slots. Block = 128 slots.
// Phase a: cooperative ef staging; b: ef->regs; c: cooperative xw1 staging;
// d: message compute in place; e: warp-chunk reduce (dst via shfl).
// ---------------------------------------------------------------------------
__global__ void __launch_bounds__(128) aggregate_kernel(
        const float* __restrict__ ef,
        const float* __restrict__ W1) {
    __shared__ ulonglong2 sW1e[16 * 16];          // 4 KB
    __shared__ float sm[128 * 66];                // 33 KB, stride 66

    int tid = threadIdx.x;
    int warp = tid >> 5, lane = tid & 31;
    sW1e[tid * 2]     = reinterpret_cast<const ulonglong2*>(W1)[1024 + tid * 2];
    sW1e[tid * 2 + 1] = reinterpret_cast<const ulonglong2*>(W1)[1024 + tid * 2 + 1];

    int slot = blockIdx.x * 128 + tid;            // N_EDGES % 128 == 0
    int4 sl = g_slot[slot];                       // {src, e, dst, pad} coalesced
    int src = sl.x;
    int e   = sl.y;
    int d   = sl.z;

    int s0 = warp * 32;

    // Phase a: cooperative ef staging (4 lanes per row, float4 each)
    #pragma unroll
    for (int it = 0; it < 4; it++) {
        int r = (lane >> 2) + 8 * it;
        int q = lane & 3;
        int eid = __shfl_sync(0xffffffffu, e, r);
        float4 f = *reinterpret_cast<const float4*>(ef + (size_t)eid * 16 + q * 4);
        float* dst = sm + (s0 + r) * 66 + q * 4;
        dst[0] = f.x; dst[1] = f.y; dst[2] = f.z; dst[3] = f.w;
    }
    __syncwarp();

    // Phase b: own ef row -> registers
    float efr[16];
    {
        const float2* mef = reinterpret_cast<const float2*>(sm + tid * 66);
        #pragma unroll
        for (int m = 0; m < 8; m++) {
            float2 v = mef[m];
            efr[2*m] = v.x; efr[2*m+1] = v.y;
        }
    }
    __syncwarp();

    // Phase c: cooperative xw1 staging (coalesced LDG.64)
    #pragma unroll 8
    for (int r = 0; r < 32; r++) {
        int sr = __shfl_sync(0xffffffffu, src, r);
        float2 v = reinterpret_cast<const float2*>(g_xw1 + (size_t)sr * 64)[lane];
        *reinterpret_cast<float2*>(sm + (s0 + r) * 66 + 2 * lane) = v;
    }
    __syncthreads();   // sW1e + staged rows ready

    // Phase d: own row -> acc, += ef @ W1e, relu, write message in place
    u64 acc[32];
    const float2* myrow = reinterpret_cast<const float2*>(sm + tid * 66);
    #pragma unroll
    for (int j = 0; j < 32; j++) {
        float2 v = myrow[j];
        acc[j] = pack2f(v.x, v.y);
    }
    #pragma unroll
    for (int i = 0; i < 16; i++) {
        u64 a = pack2(efr[i]);
        #pragma unroll
        for (int j = 0; j < 16; j++) {
            ulonglong2 w = sW1e[i * 16 + j];
            ffma2(acc[2*j], a, w.x);
            ffma2(acc[2*j+1], a, w.y);
        }
    }
    float2* myrow_w = reinterpret_cast<float2*>(sm + tid * 66);
    #pragma unroll
    for (int j = 0; j < 32; j++) {
        float lo, hi; unpack2(acc[j], lo, hi);
        myrow_w[j] = make_float2(fmaxf(lo, 0.f), fmaxf(hi, 0.f));
    }
    __syncwarp();      // warp-local messages visible

    // Phase e: warp-chunk reduce over slots [s0, s0+32); dst via shfl
    float sx = 0.0f, sy = 0.0f;
    int dprev = __shfl_sync(0xffffffffu, d, 0);
    #pragma unroll 4
    for (int t = 0; t < 32; t++) {
        int dcur = __shfl_sync(0xffffffffu, d, t);   // warp-uniform
        if (dcur != dprev) {                         // warp-uniform branch
            red_add_v2(g_agg + (size_t)dprev * 64 + 2 * lane, sx, sy);
            sx = 0.0f; sy = 0.0f;
            dprev = dcur;
        }
        float2 v = *reinterpret_cast<const float2*>(sm + (s0 + t) * 66 + 2 * lane);
        sx += v.x; sy += v.y;
    }
    red_add_v2(g_agg + (size_t)dprev * 64 + 2 * lane, sx, sy);
}

// ---------------------------------------------------------------------------
// K5: fused update+LN (nodeA folded via Wc/bc), M=2 node blocking.
// Tail: re-zero g_cnt / g_agg rows (re-establishes the entry invariant).
// ---------------------------------------------------------------------------
__global__ void __launch_bounds__(128) nodeB_kernel(
        const float* __restrict__ x,
        const float* __restrict__ W3,
        const float* __restrict__ b3,
        const float* __restrict__ gamma,
        const float* __restrict__ beta,
        float* __restrict__ out) {
    __shared__ ulonglong2 sW[128 * 16];  // 32 KB: rows 0..63 W3 top, 64..127 Wc
    __shared__ float sb3[64], sbc[64], sg[64], sbt[64];
    int tid = threadIdx.x;
    const ulonglong2* W3v = reinterpret_cast<const ulonglong2*>(W3);
    const ulonglong2* Wcv = reinterpret_cast<const ulonglong2*>(g_wc);
    for (int idx = tid; idx < 64 * 16; idx += 128) {
        sW[idx] = W3v[idx];
        sW[64 * 16 + idx] = Wcv[idx];
    }
    if (tid < 64) { sb3[tid] = b3[tid]; sbc[tid] = g_bc[tid]; sg[tid] = gamma[tid]; sbt[tid] = beta[tid]; }
    __syncthreads();

    int n0 = blockIdx.x * 256 + tid;
    int n1 = n0 + 128;
    bool vA = (n0 < N_NODES), vB = (n1 < N_NODES);
    int nA = vA ? n0 : 0, nB = vB ? n1 : 0;

    float cntA = (float)g_cnt[nA];
    float cntB = (float)g_cnt[nB];
    float invA = 1.0f / (cntA + 1e-8f), invB = 1.0f / (cntB + 1e-8f);
    float bsA = cntA * invA, bsB = cntB * invB;

    u64 accA[32], accB[32];
    #pragma unroll
    for (int j = 0; j < 32; j++) {
        accA[j] = pack2f(fmaf(bsA, sbc[2*j], sb3[2*j]), fmaf(bsA, sbc[2*j+1], sb3[2*j+1]));
        accB[j] = pack2f(fmaf(bsB, sbc[2*j], sb3[2*j]), fmaf(bsB, sbc[2*j+1], sb3[2*j+1]));
    }

    const float4* xA = reinterpret_cast<const float4*>(x + (size_t)nA * 64);
    const float4* xB = reinterpret_cast<const float4*>(x + (size_t)nB * 64);
    const float4* aA = reinterpret_cast<const float4*>(g_agg + (size_t)nA * 64);
    const float4* aB = reinterpret_cast<const float4*>(g_agg + (size_t)nB * 64);

    #pragma unroll 1
    for (int c = 0; c < 8; c++) {
        bool isx = (c < 4);
        const float4* pA = isx ? (xA + c * 4) : (aA + (c - 4) * 4);
        const float4* pB = isx ? (xB + c * 4) : (aB + (c - 4) * 4);
        float va[16], vb[16];
        #pragma unroll
        for (int j = 0; j < 4; j++) {
            float4 fa = pA[j];
            float4 fb = pB[j];
            va[4*j] = fa.x; va[4*j+1] = fa.y; va[4*j+2] = fa.z; va[4*j+3] = fa.w;
            vb[4*j] = fb.x; vb[4*j+1] = fb.y; vb[4*j+2] = fb.z; vb[4*j+3] = fb.w;
        }
        if (!isx) {
            #pragma unroll
            for (int j = 0; j < 16; j++) { va[j] *= invA; vb[j] *= invB; }
        }
        #pragma unroll
        for (int i = 0; i < 16; i++) {
            u64 a0 = pack2(va[i]);
            u64 a1 = pack2(vb[i]);
            #pragma unroll
            for (int j = 0; j < 16; j++) {
                ulonglong2 w = sW[(c * 16 + i) * 16 + j];
                ffma2(accA[2*j], a0, w.x); ffma2(accA[2*j+1], a0, w.y);
                ffma2(accB[2*j], a1, w.x); ffma2(accB[2*j+1], a1, w.y);
            }
        }
    }

    // finalize node A then node B (reuse registers); re-zero scratch
    float4 z = make_float4(0.f, 0.f, 0.f, 0.f);
    #pragma unroll 1
    for (int m = 0; m < 2; m++) {
        bool valid = m ? vB : vA;
        if (!valid) continue;
        int n = m ? n1 : n0;
        u64* acc = m ? accB : accA;
        const float4* xr = reinterpret_cast<const float4*>(x + (size_t)n * 64);

        float u[64];
        #pragma unroll
        for (int j = 0; j < 16; j++) {
            float4 f = xr[j];
            float a0, a1, a2, a3;
            unpack2(acc[2*j],   a0, a1);
            unpack2(acc[2*j+1], a2, a3);
            u[4*j]   = fmaxf(a0, 0.0f) + f.x;
            u[4*j+1] = fmaxf(a1, 0.0f) + f.y;
            u[4*j+2] = fmaxf(a2, 0.0f) + f.z;
            u[4*j+3] = fmaxf(a3, 0.0f) + f.w;
        }
        float s = 0.0f, ss = 0.0f;
        #pragma unroll
        for (int j = 0; j < 64; j++) { s += u[j]; ss = fmaf(u[j], u[j], ss); }
        float mu  = s * (1.0f / 64.0f);
        float var = ss * (1.0f / 64.0f) - mu * mu;
        float r   = rsqrtf(var + 1e-5f);

        float4* o = reinterpret_cast<float4*>(out + (size_t)n * 64);
        float4* az = reinterpret_cast<float4*>(g_agg + (size_t)n * 64);
        #pragma unroll
        for (int j = 0; j < 16; j++) {
            float4 v;
            v.x = (u[4*j]   - mu) * r * sg[4*j]   + sbt[4*j];
            v.y = (u[4*j+1] - mu) * r * sg[4*j+1] + sbt[4*j+1];
            v.z = (u[4*j+2] - mu) * r * sg[4*j+2] + sbt[4*j+2];
            v.w = (u[4*j+3] - mu) * r * sg[4*j+3] + sbt[4*j+3];
            o[j] = v;
            az[j] = z;
        }
        g_cnt[n] = 0;
    }
}

// ---------------------------------------------------------------------------
extern "C" void kernel_launch(void* const* d_in, const int* in_sizes, int n_in,
                              void* d_out, int out_size) {
    const float* x     = (const float*)d_in[0];
    const int*   ei    = (const int*)  d_in[1];
    const float* ef    = (const float*)d_in[2];
    const float* W1    = (const float*)d_in[3];
    const float* b1    = (const float*)d_in[4];
    const float* W2    = (const float*)d_in[5];
    const float* b2    = (const float*)d_in[6];
    const float* W3    = (const float*)d_in[7];
    const float* b3    = (const float*)d_in[8];
    const float* gamma = (const float*)d_in[9];
    const float* beta  = (const float*)d_in[10];
    float* out = (float*)d_out;

    (void)in_sizes; (void)n_in; (void)out_size;

    const int nb256 = (N_NODES + 255) / 256;

    fusedA_kernel<<<PC_BLOCKS + CNT_BLOCKS + PREP_BLOCKS, 128>>>(
        x, W1, b1, ei, W2, W3, b2);
    scanA_kernel<<<NB_SCAN, 256>>>();
    scanC_kernel<<<NB_SCAN, 256>>>();
    place_kernel<<<N_EDGES / 256, 256>>>(ei);
    aggregate_kernel<<<N_EDGES / 128, 128>>>(ef, W1);
    nodeB_kernel<<<nb256, 128>>>(x, W3, b3, gamma, beta, out);
}